// round 13
// baseline (speedup 1.0000x reference)
#include <cuda_runtime.h>
#include <cstdint>
#include <math.h>

#define PLANE 19660800ll
#define NSTAGE 640            // 8KB half-image stages per K-half
#define ITERS2 320            // outer iters (2 stages each)
#define STGB  8192
#define SMEMSZ (6*STGB + 1024)
#define HALF_ELEMS 2097152u   // 4096*512

// packed fp16 B tiles: [jt 0..3][chunk 0..1279][16KB SW128 tile image]
__device__ uint8_t g_wp[4ull*1280ull*16384ull];
// K-split partial sums: [2][4096*512] fp32
__device__ float g_part[2ull*HALF_ELEMS];

static __device__ __forceinline__ uint32_t s2u(const void* p){
    uint32_t a;
    asm("{ .reg .u64 t; cvta.to.shared.u64 t, %1; cvt.u32.u64 %0, t; }":"=r"(a):"l"(p));
    return a;
}
static __device__ __forceinline__ uint32_t cvt2(float s, float c){
    uint32_t r;  // lo = c (k even), hi = s (k odd)
    asm("cvt.rn.f16x2.f32 %0, %1, %2;" : "=r"(r) : "f"(s), "f"(c));
    return r;
}
static __device__ __forceinline__ void cp16(uint32_t dst, const void* src){
    asm volatile("cp.async.cg.shared.global [%0], [%1], 16;" :: "r"(dst), "l"(src) : "memory");
}
static __device__ __forceinline__ void ldsm4(uint32_t* r, uint32_t a){
    asm volatile("ldmatrix.sync.aligned.m8n8.x4.shared.b16 {%0,%1,%2,%3}, [%4];"
        : "=r"(r[0]), "=r"(r[1]), "=r"(r[2]), "=r"(r[3]) : "r"(a));
}
static __device__ __forceinline__ void mma16(float* d, const uint32_t* a, uint32_t b0, uint32_t b1){
    asm volatile("mma.sync.aligned.m16n8k16.row.col.f32.f16.f16.f32 "
        "{%0,%1,%2,%3}, {%4,%5,%6,%7}, {%8,%9}, {%0,%1,%2,%3};"
        : "+f"(d[0]), "+f"(d[1]), "+f"(d[2]), "+f"(d[3])
        : "r"(a[0]), "r"(a[1]), "r"(a[2]), "r"(a[3]), "r"(b0), "r"(b1));
}

// ---------- repack: fp32 coeffs -> fp16 pre-swizzled SW128 tile images (+eps sign), 4 pairs/thread ----------
__global__ void __launch_bounds__(256) kan_repack(const float* __restrict__ cf){
    uint32_t t  = blockIdx.x * 256u + threadIdx.x;   // 5,242,880 threads, 4 words each
    uint32_t w4 = t & 7u;                            // 16B group within row
    uint32_t n  = (t >> 3) & 127u;                   // row (output feature in tile)
    uint32_t rest = t >> 10;
    uint32_t cch = rest % 1280u;                     // chunk
    uint32_t jt  = rest / 1280u;                     // N tile
    uint32_t p0 = cch * 32u + w4 * 4u;               // first pair index (mult of 4)
    uint32_t i = p0 / 320u;
    uint32_t g0 = p0 - i * 320u;                     // group never crosses i boundary
    uint32_t j = jt * 128u + n;
    float4 a = make_float4(0.f,0.f,0.f,0.f), b = make_float4(0.f,0.f,0.f,0.f);
    if (g0 < 300u){                                  // 300 % 4 == 0: fully in or fully out
        size_t ix = ((size_t)j * 128 + i) * 300 + g0;    // 300 % 4 == 0 -> 16B aligned
        a = *(const float4*)(cf + ix);               // cos coeffs
        b = *(const float4*)(cf + PLANE + ix);       // sin coeffs
    }
    if (((g0 >> 2) & 3u) >= 2u){                     // eps sign, constant over the group
        a.x=-a.x; a.y=-a.y; a.z=-a.z; a.w=-a.w;
        b.x=-b.x; b.y=-b.y; b.z=-b.z; b.w=-b.w;
    }
    uint4 o;
    asm("cvt.rn.f16x2.f32 %0, %1, %2;" : "=r"(o.x) : "f"(b.x), "f"(a.x));
    asm("cvt.rn.f16x2.f32 %0, %1, %2;" : "=r"(o.y) : "f"(b.y), "f"(a.y));
    asm("cvt.rn.f16x2.f32 %0, %1, %2;" : "=r"(o.z) : "f"(b.z), "f"(a.z));
    asm("cvt.rn.f16x2.f32 %0, %1, %2;" : "=r"(o.w) : "f"(b.w), "f"(a.w));
    uint32_t off = n * 128u + w4 * 16u;
    off ^= (off >> 3) & 0x70u;                       // SW128 pre-swizzle (16B-group invariant)
    *(uint4*)(g_wp + ((size_t)(jt * 1280u + cch) << 14) + off) = o;
}

// ---------- GEMM: K-split x2 -> 512 CTAs (4/SM), tile 128M x 64N, 6-slot ring, 2 stages/barrier ----------
__global__ void __launch_bounds__(128,4) kan_gemm(const float* __restrict__ x){
    extern __shared__ uint8_t dsm[];
    uint32_t stg0 = (s2u(dsm) + 1023u) & ~1023u;
    int tid = threadIdx.x, l = tid & 31, wm = tid >> 5;   // 4 M-warps, 1 N-col
    int mt = blockIdx.x & 31;                             // 32 M tiles
    int jt = (blockIdx.x >> 5) & 7;                       // 8 N tiles of 64 cols
    int ks = blockIdx.x >> 8;                             // K half 0/1
    int p0 = l & 3;
    const uint8_t* wsrc = g_wp + (((size_t)(jt >> 1) * 1280u) << 14)
                               + (size_t)(jt & 1) * 8192u
                               + ((size_t)ks * 640u << 14);
    float* pout = g_part + (size_t)ks * HALF_ELEMS;
    int fbase = ks * 64;

    float acc[2][8][4];
    #pragma unroll
    for (int a = 0; a < 2; ++a)
        #pragma unroll
        for (int b = 0; b < 8; ++b)
            #pragma unroll
            for (int c = 0; c < 4; ++c) acc[a][b][c] = 0.f;

    float cP[4], cC[4], sP[4], sC[4], t2[4];   // active chains (no shadow regs)
    float nxv[4];                              // prefetched x for next reseed

    // inline reseed of chain c from nxv[c]
    #define SEEDA(c) do { \
        float s1, c1; sincosf(nxv[c], &s1, &c1); \
        float c2v = fmaf(2.f*c1, c1, -1.f), s2v = 2.f*c1*s1; \
        float c3v = fmaf(2.f*c1, c2v, -c1), s3v = fmaf(2.f*c1, s2v, -s1); \
        float c4v = fmaf(2.f*c1, c3v, -c2v), s4v = fmaf(2.f*c1, s3v, -s2v); \
        t2[c] = 2.f*c4v; \
        float Ac, As, Bc, Bs; \
        if      (p0 == 0){ Ac=c1;  As=s1;  Bc=c3v; Bs=s3v; } \
        else if (p0 == 1){ Ac=c2v; As=s2v; Bc=c2v; Bs=s2v; } \
        else if (p0 == 2){ Ac=c3v; As=s3v; Bc=c1;  Bs=s1;  } \
        else             { Ac=c4v; As=s4v; Bc=1.f; Bs=0.f; } \
        cC[c] = Ac; sC[c] = As; cP[c] = -Bc; sP[c] = Bs; \
    } while (0)

    // prologue: prefetch x for first feature; load stages 0..3 as 2 commit groups
    #pragma unroll
    for (int c = 0; c < 4; ++c){
        int m = mt*128 + wm*32 + c*8 + (l >> 2);
        nxv[c] = __ldg(x + (size_t)m*128 + fbase);
    }
    #pragma unroll
    for (int s = 0; s < 4; ++s){
        #pragma unroll
        for (int q = 0; q < 4; ++q)
            cp16(stg0 + s*STGB + tid*64 + q*16, wsrc + (size_t)s*16384u + tid*64 + q*16);
        if (s & 1) asm volatile("cp.async.commit_group;" ::: "memory");
    }

    int sif = 0, feat = 0, slotA = 0;
    for (int it2 = 0; it2 < ITERS2; ++it2){
        asm volatile("cp.async.wait_group 1;" ::: "memory");
        __syncthreads();
        {   // prefetch stages 2*it2+4, +5 into the pair consumed last outer-iter
            int ns = 2*it2 + 4;
            int pf = slotA + 4; if (pf >= 6) pf -= 6;
            if (ns < NSTAGE){
                #pragma unroll
                for (int h = 0; h < 2; ++h){
                    uint32_t d0 = stg0 + (uint32_t)(pf + h)*STGB + (uint32_t)tid*64u;
                    const uint8_t* s0 = wsrc + (size_t)(ns + h)*16384u + (size_t)tid*64u;
                    #pragma unroll
                    for (int q = 0; q < 4; ++q) cp16(d0 + q*16, s0 + q*16);
                }
            }
            asm volatile("cp.async.commit_group;" ::: "memory");
        }
        if (sif == 0){
            SEEDA(0); SEEDA(1); SEEDA(2); SEEDA(3);
            feat++;
        }
        if (sif == 3){
            int fn = fbase + feat; if (fn > 127) fn = 127;
            #pragma unroll
            for (int c = 0; c < 4; ++c){
                int m = mt*128 + wm*32 + c*8 + (l >> 2);
                nxv[c] = __ldg(x + (size_t)m*128 + fn);
            }
        }
        sif = (sif + 1 == 5) ? 0 : sif + 1;

        #pragma unroll
        for (int t = 0; t < 8; ++t){
            uint32_t sb = stg0 + (uint32_t)(slotA + (t >> 2))*STGB;
            int tt = t & 3;
            // B: 4x ldmatrix.x4 covering n64 x k16
            uint32_t bq[4][4];
            #pragma unroll
            for (int b = 0; b < 4; ++b){
                uint32_t nl = (uint32_t)(b*16 + (l & 7) + (((l >> 3) & 1) << 3));
                uint32_t ksw = (uint32_t)(tt*2 + (l >> 4));
                uint32_t off = nl*128u + ksw*16u;
                off ^= (off >> 3) & 0x70u;
                ldsm4(bq[b], sb + off);
            }
            // A: advance 4 chains 2 steps, build two m16k16 frags
            uint32_t alo[4], ahi[4];
            #pragma unroll
            for (int c = 0; c < 4; ++c){
                alo[c] = cvt2(sC[c], cC[c]);
                float cn1 = fmaf( t2[c], cC[c], cP[c]);
                float sn1 = fmaf( t2[c], sC[c], sP[c]);
                ahi[c] = cvt2(sn1, cn1);
                float cn2 = fmaf(-t2[c], cn1, cC[c]);
                float sn2 = fmaf(-t2[c], sn1, sC[c]);
                cP[c] = cn1; cC[c] = cn2; sP[c] = sn1; sC[c] = sn2;
            }
            uint32_t af0[4] = {alo[0], alo[1], ahi[0], ahi[1]};
            uint32_t af1[4] = {alo[2], alo[3], ahi[2], ahi[3]};
            #pragma unroll
            for (int nf = 0; nf < 8; ++nf){
                uint32_t b0 = bq[nf >> 1][nf & 1], b1 = bq[nf >> 1][(nf & 1) + 2];
                mma16(acc[0][nf], af0, b0, b1);
                mma16(acc[1][nf], af1, b0, b1);
            }
        }
        slotA += 2; if (slotA == 6) slotA = 0;
    }

    // epilogue: fp32 partials -> scratch (tile 128 x 64)
    #pragma unroll
    for (int mf = 0; mf < 2; ++mf){
        int r = mt*128 + wm*32 + mf*16 + (l >> 2);
        #pragma unroll
        for (int nf = 0; nf < 8; ++nf){
            int c = jt*64 + nf*8 + p0*2;
            float2 v0; v0.x = acc[mf][nf][0]; v0.y = acc[mf][nf][1];
            float2 v1; v1.x = acc[mf][nf][2]; v1.y = acc[mf][nf][3];
            *(float2*)(pout + (size_t)r*512 + c)     = v0;
            *(float2*)(pout + (size_t)(r+8)*512 + c) = v1;
        }
    }
}

// ---------- reduce: out = part0 + part1 ----------
__global__ void __launch_bounds__(256) kan_reduce(float* __restrict__ out){
    uint32_t i = blockIdx.x * 256u + threadIdx.x;   // float4 index, 524288 total
    const float4* a = (const float4*)g_part;
    const float4* b = (const float4*)(g_part + HALF_ELEMS);
    float4 va = a[i], vb = b[i];
    float4 v; v.x = va.x + vb.x; v.y = va.y + vb.y; v.z = va.z + vb.z; v.w = va.w + vb.w;
    ((float4*)out)[i] = v;
}

extern "C" void kernel_launch(void* const* d_in, const int* in_sizes, int n_in,
                              void* d_out, int out_size){
    const float* x  = (const float*)d_in[0];
    const float* cf = (const float*)d_in[1];
    kan_repack<<<20480, 256>>>(cf);
    cudaFuncSetAttribute(kan_gemm, cudaFuncAttributeMaxDynamicSharedMemorySize, SMEMSZ);
    kan_gemm<<<512, 128, SMEMSZ>>>(x);
    kan_reduce<<<2048, 256>>>((float*)d_out);
}

// round 14
// speedup vs baseline: 1.1964x; 1.1964x over previous
#include <cuda_runtime.h>
#include <cstdint>
#include <math.h>

#define PLANE 19660800ll
#define ITERS 320             // 8KB half-image stages per K-quarter
#define STGB  8192
#define SMEMSZ (4*STGB + 1024)
#define QELEMS 2097152u       // 4096*512

// packed fp16 B tiles: [jt 0..3][chunk 0..1279][16KB SW128 tile image]
__device__ uint8_t g_wp[4ull*1280ull*16384ull];
// K-split partial sums: [4][4096*512] fp32
__device__ float g_part[4ull*QELEMS];

static __device__ __forceinline__ uint32_t s2u(const void* p){
    uint32_t a;
    asm("{ .reg .u64 t; cvta.to.shared.u64 t, %1; cvt.u32.u64 %0, t; }":"=r"(a):"l"(p));
    return a;
}
static __device__ __forceinline__ uint32_t cvt2(float s, float c){
    uint32_t r;  // lo = c (k even), hi = s (k odd)
    asm("cvt.rn.f16x2.f32 %0, %1, %2;" : "=r"(r) : "f"(s), "f"(c));
    return r;
}
static __device__ __forceinline__ void cp16(uint32_t dst, const void* src){
    asm volatile("cp.async.cg.shared.global [%0], [%1], 16;" :: "r"(dst), "l"(src) : "memory");
}
static __device__ __forceinline__ void ldsm4(uint32_t* r, uint32_t a){
    asm volatile("ldmatrix.sync.aligned.m8n8.x4.shared.b16 {%0,%1,%2,%3}, [%4];"
        : "=r"(r[0]), "=r"(r[1]), "=r"(r[2]), "=r"(r[3]) : "r"(a));
}
static __device__ __forceinline__ void mma16(float* d, const uint32_t* a, uint32_t b0, uint32_t b1){
    asm volatile("mma.sync.aligned.m16n8k16.row.col.f32.f16.f16.f32 "
        "{%0,%1,%2,%3}, {%4,%5,%6,%7}, {%8,%9}, {%0,%1,%2,%3};"
        : "+f"(d[0]), "+f"(d[1]), "+f"(d[2]), "+f"(d[3])
        : "r"(a[0]), "r"(a[1]), "r"(a[2]), "r"(a[3]), "r"(b0), "r"(b1));
}

// ---------- repack: fp32 coeffs -> fp16 pre-swizzled SW128 tile images (+eps sign), 4 pairs/thread ----------
__global__ void __launch_bounds__(256) kan_repack(const float* __restrict__ cf){
    uint32_t t  = blockIdx.x * 256u + threadIdx.x;   // 5,242,880 threads, 4 words each
    uint32_t w4 = t & 7u;                            // 16B group within row
    uint32_t n  = (t >> 3) & 127u;                   // row (output feature in tile)
    uint32_t rest = t >> 10;
    uint32_t cch = rest % 1280u;                     // chunk
    uint32_t jt  = rest / 1280u;                     // N tile
    uint32_t p0 = cch * 32u + w4 * 4u;               // first pair index (mult of 4)
    uint32_t i = p0 / 320u;
    uint32_t g0 = p0 - i * 320u;                     // group never crosses i boundary
    uint32_t j = jt * 128u + n;
    float4 a = make_float4(0.f,0.f,0.f,0.f), b = make_float4(0.f,0.f,0.f,0.f);
    if (g0 < 300u){                                  // 300 % 4 == 0: fully in or fully out
        size_t ix = ((size_t)j * 128 + i) * 300 + g0;
        a = *(const float4*)(cf + ix);               // cos coeffs
        b = *(const float4*)(cf + PLANE + ix);       // sin coeffs
    }
    if (((g0 >> 2) & 3u) >= 2u){                     // eps sign, constant over the group
        a.x=-a.x; a.y=-a.y; a.z=-a.z; a.w=-a.w;
        b.x=-b.x; b.y=-b.y; b.z=-b.z; b.w=-b.w;
    }
    uint4 o;
    asm("cvt.rn.f16x2.f32 %0, %1, %2;" : "=r"(o.x) : "f"(b.x), "f"(a.x));
    asm("cvt.rn.f16x2.f32 %0, %1, %2;" : "=r"(o.y) : "f"(b.y), "f"(a.y));
    asm("cvt.rn.f16x2.f32 %0, %1, %2;" : "=r"(o.z) : "f"(b.z), "f"(a.z));
    asm("cvt.rn.f16x2.f32 %0, %1, %2;" : "=r"(o.w) : "f"(b.w), "f"(a.w));
    uint32_t off = n * 128u + w4 * 16u;
    off ^= (off >> 3) & 0x70u;                       // SW128 pre-swizzle (16B-group invariant)
    *(uint4*)(g_wp + ((size_t)(jt * 1280u + cch) << 14) + off) = o;
}

// ---------- GEMM: K-split x4 -> 1024 CTAs (4/SM, work-steal balanced), tile 128M x 64N ----------
__global__ void __launch_bounds__(128,4) kan_gemm(const float* __restrict__ x){
    extern __shared__ uint8_t dsm[];
    uint32_t stg0 = (s2u(dsm) + 1023u) & ~1023u;
    int tid = threadIdx.x, l = tid & 31, wm = tid >> 5;   // 4 M-warps, 1 N-col
    int mt = blockIdx.x & 31;                             // 32 M tiles
    int jt = (blockIdx.x >> 5) & 7;                       // 8 N tiles of 64 cols
    int ks = blockIdx.x >> 8;                             // K quarter 0..3
    int p0 = l & 3;
    const uint8_t* wsrc = g_wp + (((size_t)(jt >> 1) * 1280u) << 14)
                               + (size_t)(jt & 1) * 8192u
                               + ((size_t)ks * 320u << 14);
    float* pout = g_part + (size_t)ks * QELEMS;
    int fbase = ks * 32;

    float acc[2][8][4];
    #pragma unroll
    for (int a = 0; a < 2; ++a)
        #pragma unroll
        for (int b = 0; b < 8; ++b)
            #pragma unroll
            for (int c = 0; c < 4; ++c) acc[a][b][c] = 0.f;

    float cP[4], cC[4], sP[4], sC[4], t2[4];              // active chains
    float ncP[4], ncC[4], nsP[4], nsC[4], nt2[4];         // shadow seeds (next feature)

    #define SEED(c, f) do { \
        int m_ = mt*128 + wm*32 + (c)*8 + (l >> 2); \
        float xv = __ldg(x + (size_t)m_*128 + (f)); \
        float s1, c1; sincosf(xv, &s1, &c1); \
        float c2v = fmaf(2.f*c1, c1, -1.f), s2v = 2.f*c1*s1; \
        float c3v = fmaf(2.f*c1, c2v, -c1), s3v = fmaf(2.f*c1, s2v, -s1); \
        float c4v = fmaf(2.f*c1, c3v, -c2v), s4v = fmaf(2.f*c1, s3v, -s2v); \
        nt2[c] = 2.f*c4v; \
        float Ac, As, Bc, Bs; \
        if      (p0 == 0){ Ac=c1;  As=s1;  Bc=c3v; Bs=s3v; } \
        else if (p0 == 1){ Ac=c2v; As=s2v; Bc=c2v; Bs=s2v; } \
        else if (p0 == 2){ Ac=c3v; As=s3v; Bc=c1;  Bs=s1;  } \
        else             { Ac=c4v; As=s4v; Bc=1.f; Bs=0.f; } \
        ncC[c] = Ac; nsC[c] = As; ncP[c] = -Bc; nsP[c] = Bs; \
    } while (0)

    // prologue: seed first feature of this K-quarter, prefetch stages 0..2
    #pragma unroll
    for (int c = 0; c < 4; ++c) SEED(c, fbase);
    #pragma unroll
    for (int s = 0; s < 3; ++s){
        #pragma unroll
        for (int q = 0; q < 4; ++q)
            cp16(stg0 + s*STGB + tid*64 + q*16, wsrc + (size_t)s*16384u + tid*64 + q*16);
        asm volatile("cp.async.commit_group;" ::: "memory");
    }

    int sif = 0, feat = 0;
    for (int it = 0; it < ITERS; ++it){
        asm volatile("cp.async.wait_group 2;" ::: "memory");
        __syncthreads();
        {   int ns = it + 3;
            if (ns < ITERS){
                uint32_t d0 = stg0 + (ns & 3)*STGB + tid*64;
                const uint8_t* s0 = wsrc + (size_t)ns*16384u + tid*64;
                #pragma unroll
                for (int q = 0; q < 4; ++q) cp16(d0 + q*16, s0 + q*16);
            }
            asm volatile("cp.async.commit_group;" ::: "memory");
        }
        if (sif == 0){
            #pragma unroll
            for (int c = 0; c < 4; ++c){
                cC[c] = ncC[c]; sC[c] = nsC[c]; cP[c] = ncP[c]; sP[c] = nsP[c]; t2[c] = nt2[c];
            }
            feat++;
        }
        if (sif == 4){
            int fn = fbase + feat; if (fn > 127) fn = 127;
            #pragma unroll
            for (int c = 0; c < 4; ++c) SEED(c, fn);
        }
        sif = (sif + 1 == 10) ? 0 : sif + 1;

        uint32_t sb = stg0 + (it & 3)*STGB;
        #pragma unroll
        for (int t = 0; t < 4; ++t){
            uint32_t bq[4][4];
            #pragma unroll
            for (int b = 0; b < 4; ++b){
                uint32_t nl = (uint32_t)(b*16 + (l & 7) + (((l >> 3) & 1) << 3));
                uint32_t ksw = (uint32_t)(t*2 + (l >> 4));
                uint32_t off = nl*128u + ksw*16u;
                off ^= (off >> 3) & 0x70u;
                ldsm4(bq[b], sb + off);
            }
            uint32_t alo[4], ahi[4];
            #pragma unroll
            for (int c = 0; c < 4; ++c){
                alo[c] = cvt2(sC[c], cC[c]);
                float cn1 = fmaf( t2[c], cC[c], cP[c]);
                float sn1 = fmaf( t2[c], sC[c], sP[c]);
                ahi[c] = cvt2(sn1, cn1);
                float cn2 = fmaf(-t2[c], cn1, cC[c]);
                float sn2 = fmaf(-t2[c], sn1, sC[c]);
                cP[c] = cn1; cC[c] = cn2; sP[c] = sn1; sC[c] = sn2;
            }
            uint32_t af0[4] = {alo[0], alo[1], ahi[0], ahi[1]};
            uint32_t af1[4] = {alo[2], alo[3], ahi[2], ahi[3]};
            #pragma unroll
            for (int nf = 0; nf < 8; ++nf){
                uint32_t b0 = bq[nf >> 1][nf & 1], b1 = bq[nf >> 1][(nf & 1) + 2];
                mma16(acc[0][nf], af0, b0, b1);
                mma16(acc[1][nf], af1, b0, b1);
            }
        }
    }

    // epilogue: fp32 partials -> scratch plane (tile 128 x 64)
    #pragma unroll
    for (int mf = 0; mf < 2; ++mf){
        int r = mt*128 + wm*32 + mf*16 + (l >> 2);
        #pragma unroll
        for (int nf = 0; nf < 8; ++nf){
            int c = jt*64 + nf*8 + p0*2;
            float2 v0; v0.x = acc[mf][nf][0]; v0.y = acc[mf][nf][1];
            float2 v1; v1.x = acc[mf][nf][2]; v1.y = acc[mf][nf][3];
            *(float2*)(pout + (size_t)r*512 + c)     = v0;
            *(float2*)(pout + (size_t)(r+8)*512 + c) = v1;
        }
    }
}

// ---------- reduce: out = part0 + part1 + part2 + part3 (fixed order, deterministic) ----------
__global__ void __launch_bounds__(256) kan_reduce(float* __restrict__ out){
    uint32_t i = blockIdx.x * 256u + threadIdx.x;   // float4 index, 524288 total
    const float4* p0 = (const float4*)g_part;
    const float4* p1 = (const float4*)(g_part + (size_t)QELEMS);
    const float4* p2 = (const float4*)(g_part + 2ull*QELEMS);
    const float4* p3 = (const float4*)(g_part + 3ull*QELEMS);
    float4 a = p0[i], b = p1[i], c = p2[i], d = p3[i];
    float4 v;
    v.x = (a.x + b.x) + (c.x + d.x);
    v.y = (a.y + b.y) + (c.y + d.y);
    v.z = (a.z + b.z) + (c.z + d.z);
    v.w = (a.w + b.w) + (c.w + d.w);
    ((float4*)out)[i] = v;
}

extern "C" void kernel_launch(void* const* d_in, const int* in_sizes, int n_in,
                              void* d_out, int out_size){
    const float* x  = (const float*)d_in[0];
    const float* cf = (const float*)d_in[1];
    kan_repack<<<20480, 256>>>(cf);
    cudaFuncSetAttribute(kan_gemm, cudaFuncAttributeMaxDynamicSharedMemorySize, SMEMSZ);
    kan_gemm<<<1024, 128, SMEMSZ>>>(x);
    kan_reduce<<<2048, 256>>>((float*)d_out);
}

// round 15
// speedup vs baseline: 1.2127x; 1.0136x over previous
#include <cuda_runtime.h>
#include <cstdint>
#include <math.h>

#define PLANE 19660800ll
#define ITERS 160             // 8KB half-image stages per K-eighth
#define STGB  8192
#define SMEMSZ (4*STGB + 1024)
#define QELEMS 2097152u       // 4096*512

// packed fp16 B tiles: [jt 0..3][chunk 0..1279][16KB SW128 tile image]
__device__ uint8_t g_wp[4ull*1280ull*16384ull];
// K-split partial sums: [8][4096*512] fp32
__device__ float g_part[8ull*QELEMS];

static __device__ __forceinline__ uint32_t s2u(const void* p){
    uint32_t a;
    asm("{ .reg .u64 t; cvta.to.shared.u64 t, %1; cvt.u32.u64 %0, t; }":"=r"(a):"l"(p));
    return a;
}
static __device__ __forceinline__ uint32_t cvt2(float s, float c){
    uint32_t r;  // lo = c (k even), hi = s (k odd)
    asm("cvt.rn.f16x2.f32 %0, %1, %2;" : "=r"(r) : "f"(s), "f"(c));
    return r;
}
static __device__ __forceinline__ void cp16(uint32_t dst, const void* src){
    asm volatile("cp.async.cg.shared.global [%0], [%1], 16;" :: "r"(dst), "l"(src) : "memory");
}
static __device__ __forceinline__ void ldsm4(uint32_t* r, uint32_t a){
    asm volatile("ldmatrix.sync.aligned.m8n8.x4.shared.b16 {%0,%1,%2,%3}, [%4];"
        : "=r"(r[0]), "=r"(r[1]), "=r"(r[2]), "=r"(r[3]) : "r"(a));
}
static __device__ __forceinline__ void mma16(float* d, const uint32_t* a, uint32_t b0, uint32_t b1){
    asm volatile("mma.sync.aligned.m16n8k16.row.col.f32.f16.f16.f32 "
        "{%0,%1,%2,%3}, {%4,%5,%6,%7}, {%8,%9}, {%0,%1,%2,%3};"
        : "+f"(d[0]), "+f"(d[1]), "+f"(d[2]), "+f"(d[3])
        : "r"(a[0]), "r"(a[1]), "r"(a[2]), "r"(a[3]), "r"(b0), "r"(b1));
}

// ---------- repack: fp32 coeffs -> fp16 pre-swizzled SW128 tile images (+eps sign), 4 pairs/thread ----------
__global__ void __launch_bounds__(256) kan_repack(const float* __restrict__ cf){
    uint32_t t  = blockIdx.x * 256u + threadIdx.x;   // 5,242,880 threads, 4 words each
    uint32_t w4 = t & 7u;                            // 16B group within row
    uint32_t n  = (t >> 3) & 127u;                   // row (output feature in tile)
    uint32_t rest = t >> 10;
    uint32_t cch = rest % 1280u;                     // chunk
    uint32_t jt  = rest / 1280u;                     // N tile
    uint32_t p0 = cch * 32u + w4 * 4u;               // first pair index (mult of 4)
    uint32_t i = p0 / 320u;
    uint32_t g0 = p0 - i * 320u;                     // group never crosses i boundary
    uint32_t j = jt * 128u + n;
    float4 a = make_float4(0.f,0.f,0.f,0.f), b = make_float4(0.f,0.f,0.f,0.f);
    if (g0 < 300u){                                  // 300 % 4 == 0: fully in or fully out
        size_t ix = ((size_t)j * 128 + i) * 300 + g0;
        a = *(const float4*)(cf + ix);               // cos coeffs
        b = *(const float4*)(cf + PLANE + ix);       // sin coeffs
    }
    if (((g0 >> 2) & 3u) >= 2u){                     // eps sign, constant over the group
        a.x=-a.x; a.y=-a.y; a.z=-a.z; a.w=-a.w;
        b.x=-b.x; b.y=-b.y; b.z=-b.z; b.w=-b.w;
    }
    uint4 o;
    asm("cvt.rn.f16x2.f32 %0, %1, %2;" : "=r"(o.x) : "f"(b.x), "f"(a.x));
    asm("cvt.rn.f16x2.f32 %0, %1, %2;" : "=r"(o.y) : "f"(b.y), "f"(a.y));
    asm("cvt.rn.f16x2.f32 %0, %1, %2;" : "=r"(o.z) : "f"(b.z), "f"(a.z));
    asm("cvt.rn.f16x2.f32 %0, %1, %2;" : "=r"(o.w) : "f"(b.w), "f"(a.w));
    uint32_t off = n * 128u + w4 * 16u;
    off ^= (off >> 3) & 0x70u;                       // SW128 pre-swizzle (16B-group invariant)
    *(uint4*)(g_wp + ((size_t)(jt * 1280u + cch) << 14) + off) = o;
}

// ---------- GEMM: K-split x8 -> 2048 CTAs (4/SM, fine-grained tail), tile 128M x 64N ----------
__global__ void __launch_bounds__(128,4) kan_gemm(const float* __restrict__ x){
    extern __shared__ uint8_t dsm[];
    uint32_t stg0 = (s2u(dsm) + 1023u) & ~1023u;
    int tid = threadIdx.x, l = tid & 31, wm = tid >> 5;   // 4 M-warps, 1 N-col
    int mt = blockIdx.x & 31;                             // 32 M tiles
    int jt = (blockIdx.x >> 5) & 7;                       // 8 N tiles of 64 cols
    int ks = blockIdx.x >> 8;                             // K eighth 0..7
    int p0 = l & 3;
    const uint8_t* wsrc = g_wp + (((size_t)(jt >> 1) * 1280u) << 14)
                               + (size_t)(jt & 1) * 8192u
                               + ((size_t)ks * 160u << 14);
    float* pout = g_part + (size_t)ks * QELEMS;
    int fbase = ks * 16;

    float acc[2][8][4];
    #pragma unroll
    for (int a = 0; a < 2; ++a)
        #pragma unroll
        for (int b = 0; b < 8; ++b)
            #pragma unroll
            for (int c = 0; c < 4; ++c) acc[a][b][c] = 0.f;

    float cP[4], cC[4], sP[4], sC[4], t2[4];              // active chains
    float ncP[4], ncC[4], nsP[4], nsC[4], nt2[4];         // shadow seeds (next feature)

    #define SEED(c, f) do { \
        int m_ = mt*128 + wm*32 + (c)*8 + (l >> 2); \
        float xv = __ldg(x + (size_t)m_*128 + (f)); \
        float s1, c1; sincosf(xv, &s1, &c1); \
        float c2v = fmaf(2.f*c1, c1, -1.f), s2v = 2.f*c1*s1; \
        float c3v = fmaf(2.f*c1, c2v, -c1), s3v = fmaf(2.f*c1, s2v, -s1); \
        float c4v = fmaf(2.f*c1, c3v, -c2v), s4v = fmaf(2.f*c1, s3v, -s2v); \
        nt2[c] = 2.f*c4v; \
        float Ac, As, Bc, Bs; \
        if      (p0 == 0){ Ac=c1;  As=s1;  Bc=c3v; Bs=s3v; } \
        else if (p0 == 1){ Ac=c2v; As=s2v; Bc=c2v; Bs=s2v; } \
        else if (p0 == 2){ Ac=c3v; As=s3v; Bc=c1;  Bs=s1;  } \
        else             { Ac=c4v; As=s4v; Bc=1.f; Bs=0.f; } \
        ncC[c] = Ac; nsC[c] = As; ncP[c] = -Bc; nsP[c] = Bs; \
    } while (0)

    // prologue: seed first feature of this K-eighth, prefetch stages 0..2
    #pragma unroll
    for (int c = 0; c < 4; ++c) SEED(c, fbase);
    #pragma unroll
    for (int s = 0; s < 3; ++s){
        #pragma unroll
        for (int q = 0; q < 4; ++q)
            cp16(stg0 + s*STGB + tid*64 + q*16, wsrc + (size_t)s*16384u + tid*64 + q*16);
        asm volatile("cp.async.commit_group;" ::: "memory");
    }

    int sif = 0, feat = 0;
    for (int it = 0; it < ITERS; ++it){
        asm volatile("cp.async.wait_group 2;" ::: "memory");
        __syncthreads();
        {   int ns = it + 3;
            if (ns < ITERS){
                uint32_t d0 = stg0 + (ns & 3)*STGB + tid*64;
                const uint8_t* s0 = wsrc + (size_t)ns*16384u + tid*64;
                #pragma unroll
                for (int q = 0; q < 4; ++q) cp16(d0 + q*16, s0 + q*16);
            }
            asm volatile("cp.async.commit_group;" ::: "memory");
        }
        if (sif == 0){
            #pragma unroll
            for (int c = 0; c < 4; ++c){
                cC[c] = ncC[c]; sC[c] = nsC[c]; cP[c] = ncP[c]; sP[c] = nsP[c]; t2[c] = nt2[c];
            }
            feat++;
        }
        if (sif == 4){
            int fn = fbase + feat; if (fn > 127) fn = 127;
            #pragma unroll
            for (int c = 0; c < 4; ++c) SEED(c, fn);
        }
        sif = (sif + 1 == 10) ? 0 : sif + 1;

        uint32_t sb = stg0 + (it & 3)*STGB;
        #pragma unroll
        for (int t = 0; t < 4; ++t){
            uint32_t bq[4][4];
            #pragma unroll
            for (int b = 0; b < 4; ++b){
                uint32_t nl = (uint32_t)(b*16 + (l & 7) + (((l >> 3) & 1) << 3));
                uint32_t ksw = (uint32_t)(t*2 + (l >> 4));
                uint32_t off = nl*128u + ksw*16u;
                off ^= (off >> 3) & 0x70u;
                ldsm4(bq[b], sb + off);
            }
            uint32_t alo[4], ahi[4];
            #pragma unroll
            for (int c = 0; c < 4; ++c){
                alo[c] = cvt2(sC[c], cC[c]);
                float cn1 = fmaf( t2[c], cC[c], cP[c]);
                float sn1 = fmaf( t2[c], sC[c], sP[c]);
                ahi[c] = cvt2(sn1, cn1);
                float cn2 = fmaf(-t2[c], cn1, cC[c]);
                float sn2 = fmaf(-t2[c], sn1, sC[c]);
                cP[c] = cn1; cC[c] = cn2; sP[c] = sn1; sC[c] = sn2;
            }
            uint32_t af0[4] = {alo[0], alo[1], ahi[0], ahi[1]};
            uint32_t af1[4] = {alo[2], alo[3], ahi[2], ahi[3]};
            #pragma unroll
            for (int nf = 0; nf < 8; ++nf){
                uint32_t b0 = bq[nf >> 1][nf & 1], b1 = bq[nf >> 1][(nf & 1) + 2];
                mma16(acc[0][nf], af0, b0, b1);
                mma16(acc[1][nf], af1, b0, b1);
            }
        }
    }

    // epilogue: fp32 partials -> scratch plane (tile 128 x 64)
    #pragma unroll
    for (int mf = 0; mf < 2; ++mf){
        int r = mt*128 + wm*32 + mf*16 + (l >> 2);
        #pragma unroll
        for (int nf = 0; nf < 8; ++nf){
            int c = jt*64 + nf*8 + p0*2;
            float2 v0; v0.x = acc[mf][nf][0]; v0.y = acc[mf][nf][1];
            float2 v1; v1.x = acc[mf][nf][2]; v1.y = acc[mf][nf][3];
            *(float2*)(pout + (size_t)r*512 + c)     = v0;
            *(float2*)(pout + (size_t)(r+8)*512 + c) = v1;
        }
    }
}

// ---------- reduce: out = sum of 8 partial planes (fixed order, deterministic) ----------
__global__ void __launch_bounds__(256) kan_reduce(float* __restrict__ out){
    uint32_t i = blockIdx.x * 256u + threadIdx.x;   // float4 index, 524288 total
    float4 v = make_float4(0.f,0.f,0.f,0.f);
    #pragma unroll
    for (int p = 0; p < 8; ++p){
        float4 a = ((const float4*)(g_part + (size_t)p * QELEMS))[i];
        v.x += a.x; v.y += a.y; v.z += a.z; v.w += a.w;
    }
    ((float4*)out)[i] = v;
}

extern "C" void kernel_launch(void* const* d_in, const int* in_sizes, int n_in,
                              void* d_out, int out_size){
    const float* x  = (const float*)d_in[0];
    const float* cf = (const float*)d_in[1];
    kan_repack<<<20480, 256>>>(cf);
    cudaFuncSetAttribute(kan_gemm, cudaFuncAttributeMaxDynamicSharedMemorySize, SMEMSZ);
    kan_gemm<<<2048, 128, SMEMSZ>>>(x);
    kan_reduce<<<2048, 256>>>((float*)d_out);
}